// round 14
// baseline (speedup 1.0000x reference)
#include <cuda_runtime.h>
#include <cstdint>

// LorenzSDE ShARK — persistent double-buffered BULK-copy pipeline, v14.
//   Single change vs banked R8 (90.7 +/- 1.4us, DRAM ~85%): the per-tile
//   prefetch is two cp.async.bulk (UBLKCP) copies issued by one elected
//   thread, completing on per-buffer mbarriers, instead of 960 cp.async.cg
//   lane-granules (120 LDGSTS warp-instructions). Tests whether load-issue
//   overhead / request granularity contributes to the residual DRAM idle.
//   Geometry unchanged: TILE=128, BLOCK=128, 30KB data smem, grid 1024,
//   register x prefetch, streaming scalar stores.

#define BLOCK 128
#define TILE  128
#define W4        (TILE * 15 / 4)          // 480 float4 per tile per tensor
#define TILE_B    (W4 * 16)                // 7680 bytes per tensor tile
#define GRID  1024                         // 32768/1024 = 32 tiles/CTA exact

__device__ __forceinline__ uint32_t s2u(const void* p) {
    return (uint32_t)__cvta_generic_to_shared(p);
}

__device__ __forceinline__ void bulk_g2s(uint32_t dst_smem, const void* src,
                                         uint32_t bytes, uint32_t mbar) {
    asm volatile(
        "cp.async.bulk.shared::cta.global.mbarrier::complete_tx::bytes "
        "[%0], [%1], %2, [%3];"
        :: "r"(dst_smem), "l"(src), "r"(bytes), "r"(mbar) : "memory");
}

__device__ __forceinline__ void mbar_init(uint32_t mbar, uint32_t count) {
    asm volatile("mbarrier.init.shared.b64 [%0], %1;" :: "r"(mbar), "r"(count) : "memory");
}

__device__ __forceinline__ void mbar_expect_tx(uint32_t mbar, uint32_t bytes) {
    asm volatile("mbarrier.arrive.expect_tx.shared.b64 _, [%0], %1;"
                 :: "r"(mbar), "r"(bytes) : "memory");
}

__device__ __forceinline__ void mbar_wait(uint32_t mbar, uint32_t parity) {
    asm volatile(
        "{\n\t"
        ".reg .pred P;\n\t"
        "WAIT_%=: mbarrier.try_wait.parity.acquire.cta.shared::cta.b64 P, [%0], %1, 0x989680;\n\t"
        "@P bra.uni DONE_%=;\n\t"
        "bra.uni WAIT_%=;\n\t"
        "DONE_%=:\n\t"
        "}"
        :: "r"(mbar), "r"(parity) : "memory");
}

__global__ __launch_bounds__(BLOCK) void lorenz_shark_kernel(
    const float* __restrict__ g_x,
    const float* __restrict__ g_dW,
    const float* __restrict__ g_dH,
    float* __restrict__ g_out,
    int n_tiles)
{
    __shared__ float4 s_w[2][W4];            // 2 x 7.5 KB
    __shared__ float4 s_h[2][W4];            // 2 x 7.5 KB -> 30 KB data
    __shared__ alignas(8) uint64_t s_mbar[2];

    const int tid = threadIdx.x;

    const float DT  = 0.01f;
    const float CW  = 0.2f;                  // NOISE*sqrt(DT)
    const float CH  = 0.05773502691896258f;  // NOISE*sqrt(DT/12)
    const float SIG = 10.0f;
    const float RHO = 28.0f;
    const float BET = 8.0f / 3.0f;
    const float A56 = (5.0f / 6.0f) * DT;
    const float B56 = 5.0f / 6.0f;

    int tile = blockIdx.x;
    if (tile >= n_tiles) return;

    const uint32_t mb0 = s2u(&s_mbar[0]);
    const uint32_t mb1 = s2u(&s_mbar[1]);

    if (tid == 0) {
        mbar_init(mb0, 1);
        mbar_init(mb1, 1);
    }
    __syncthreads();             // mbarrier init visible before any bulk copy

    // one elected thread issues the whole tile as two bulk copies
    auto issue_tile = [&](int buf, int t) {
        const uint32_t mb = buf ? mb1 : mb0;
        mbar_expect_tx(mb, 2 * TILE_B);
        bulk_g2s(s2u(&s_w[buf][0]), g_dW + (long long)t * TILE * 15, TILE_B, mb);
        bulk_g2s(s2u(&s_h[buf][0]), g_dH + (long long)t * TILE * 15, TILE_B, mb);
    };

    // ---- prologue: tile 0 bulk-copy + x(tile 0) register prefetch ----
    if (tid == 0) issue_tile(0, tile);
    const float* xp = g_x + (long long)tile * TILE * 3 + tid * 3;
    float xr0 = __ldcs(xp + 0), xr1 = __ldcs(xp + 1), xr2 = __ldcs(xp + 2);

    int buf = 0;
    uint32_t ph0 = 0, ph1 = 0;   // per-buffer phase parity

    for (; tile < n_tiles; tile += GRID) {
        const int next = tile + GRID;

        float nx0 = 0.f, nx1 = 0.f, nx2 = 0.f;
        if (next < n_tiles) {
            // buf^1's readers finished at the previous iteration's
            // end-of-loop __syncthreads, so overwrite is safe.
            if (tid == 0) issue_tile(buf ^ 1, next);
            const float* nxp = g_x + (long long)next * TILE * 3 + tid * 3;
            nx0 = __ldcs(nxp + 0); nx1 = __ldcs(nxp + 1); nx2 = __ldcs(nxp + 2);
        }

        // wait for current tile's bulk copies (acquire orders smem reads)
        if (buf == 0) { mbar_wait(mb0, ph0); ph0 ^= 1; }
        else          { mbar_wait(mb1, ph1); ph1 ^= 1; }

        const float* w = reinterpret_cast<const float*>(s_w[buf]);
        const float* h = reinterpret_cast<const float*>(s_h[buf]);

        float y0 = xr0, y1 = xr1, y2 = xr2;

        #pragma unroll
        for (int s = 0; s < 5; ++s) {
            const float w0 = w[tid * 15 + s * 3 + 0] * CW;
            const float w1 = w[tid * 15 + s * 3 + 1] * CW;
            const float w2 = w[tid * 15 + s * 3 + 2] * CW;
            const float h0 = h[tid * 15 + s * 3 + 0] * CH;
            const float h1 = h[tid * 15 + s * 3 + 1] * CH;
            const float h2 = h[tid * 15 + s * 3 + 2] * CH;

            const float z10 = y0 + h0;
            const float z11 = y1 + h1;
            const float z12 = y2 + h2;
            const float f10 = SIG * (z11 - z10);
            const float f11 = z10 * (RHO - z12) - z11;
            const float f12 = z10 * z11 - BET * z12;
            const float z20 = y0 + A56 * f10 + B56 * w0 + h0;
            const float z21 = y1 + A56 * f11 + B56 * w1 + h1;
            const float z22 = y2 + A56 * f12 + B56 * w2 + h2;
            const float f20 = SIG * (z21 - z20);
            const float f21 = z20 * (RHO - z22) - z21;
            const float f22 = z20 * z21 - BET * z22;
            y0 = y0 + DT * (0.4f * f10 + 0.6f * f20) + w0;
            y1 = y1 + DT * (0.4f * f11 + 0.6f * f21) + w1;
            y2 = y2 + DT * (0.4f * f12 + 0.6f * f22) + w2;
        }

        // direct streaming store (warp covers contiguous 384B -> full sectors)
        float* op = g_out + (long long)tile * TILE * 3 + tid * 3;
        __stcs(op + 0, y0);
        __stcs(op + 1, y1);
        __stcs(op + 2, y2);

        // all threads' reads of s_*[buf] done before thread 0 overwrites it
        // with the bulk copy issued at the top of the next iteration.
        __syncthreads();

        xr0 = nx0; xr1 = nx1; xr2 = nx2;
        buf ^= 1;
    }
}

extern "C" void kernel_launch(void* const* d_in, const int* in_sizes, int n_in,
                              void* d_out, int out_size) {
    const float* x  = (const float*)d_in[0];
    const float* dW = (const float*)d_in[1];
    const float* dH = (const float*)d_in[2];
    float* out = (float*)d_out;

    const int n = in_sizes[0] / 3;        // 4194304, multiple of TILE
    const int n_tiles = n / TILE;         // 32768
    int grid = GRID;                      // exact 32 tiles/CTA, single wave
    if (grid > n_tiles) grid = n_tiles;
    lorenz_shark_kernel<<<grid, BLOCK>>>(x, dW, dH, out, n_tiles);
}

// round 15
// speedup vs baseline: 1.0371x; 1.0371x over previous
#include <cuda_runtime.h>
#include <cstdint>

// LorenzSDE ShARK — persistent double-buffered cp.async pipeline (FINAL).
//   Converged optimum, reproduced across R8/R10/R12/R13 (90.7 +/- 1.4us).
//   Wins:   R2 bursty->continuous cp.async pipeline      (109.0 -> 95.0us)
//           R3 register x/out, 30KB smem, 7 CTAs/SM      ( 95.0 -> 92.5us)
//           R4 exact-divisor grid + streaming hints      ( 92.5 -> 90.7us)
//   Falsified: 3-stage ring (R5 +6us), TILE=64 (R6), warp-private
//   pipelines (R7), DRAM request ordering (R9), STG.128 staging (R11 tie),
//   cp.async.bulk/mbarrier load path (R14 +3us).
//   90.7us, DRAM ~85-86% (6.8 TB/s); traffic = 604MB theoretical minimum:
//   the practical HBM-controller floor for the 11:1 read/write mix.

#define BLOCK 128
#define TILE  128
#define W4    (TILE * 15 / 4)   // 480 float4 per tile for dW (and dH)
#define GRID  1024              // 32768 / 1024 = 32 tiles per CTA, exact

__device__ __forceinline__ void cp16(void* sptr, const void* gptr) {
    uint32_t s = (uint32_t)__cvta_generic_to_shared(sptr);
    asm volatile("cp.async.cg.shared.global [%0], [%1], 16;"
                 :: "r"(s), "l"(gptr) : "memory");
}
#define CP_COMMIT() asm volatile("cp.async.commit_group;" ::: "memory")
#define CP_WAIT(N)  asm volatile("cp.async.wait_group %0;" :: "n"(N) : "memory")

__global__ __launch_bounds__(BLOCK) void lorenz_shark_kernel(
    const float* __restrict__ g_x,
    const float* __restrict__ g_dW,
    const float* __restrict__ g_dH,
    float* __restrict__ g_out,
    int n_tiles)
{
    __shared__ float4 s_w[2][W4];   // 2 x 7.5 KB
    __shared__ float4 s_h[2][W4];   // 2 x 7.5 KB -> 30 KB total, 7 CTAs/SM

    const int tid = threadIdx.x;

    const float DT  = 0.01f;
    const float CW  = 0.2f;                  // NOISE*sqrt(DT)
    const float CH  = 0.05773502691896258f;  // NOISE*sqrt(DT/12)
    const float SIG = 10.0f;
    const float RHO = 28.0f;
    const float BET = 8.0f / 3.0f;
    const float A56 = (5.0f / 6.0f) * DT;
    const float B56 = 5.0f / 6.0f;

    int tile = blockIdx.x;
    if (tile >= n_tiles) return;

    auto prefetch_wh = [&](int buf, int t) {
        const float4* gw = reinterpret_cast<const float4*>(g_dW + (long long)t * TILE * 15);
        const float4* gh = reinterpret_cast<const float4*>(g_dH + (long long)t * TILE * 15);
        #pragma unroll
        for (int i = tid; i < W4; i += BLOCK) {
            cp16(&s_w[buf][i], gw + i);
            cp16(&s_h[buf][i], gh + i);
        }
    };

    // ---- prologue: prefetch tile 0 (smem) + x(tile 0) (regs, streaming) ----
    prefetch_wh(0, tile);
    CP_COMMIT();
    const float* xp = g_x + (long long)tile * TILE * 3 + tid * 3;
    float xr0 = __ldcs(xp + 0), xr1 = __ldcs(xp + 1), xr2 = __ldcs(xp + 2);

    int buf = 0;
    for (; tile < n_tiles; tile += GRID) {
        const int next = tile + GRID;

        float nx0 = 0.f, nx1 = 0.f, nx2 = 0.f;
        if (next < n_tiles) {
            prefetch_wh(buf ^ 1, next);
            CP_COMMIT();
            const float* nxp = g_x + (long long)next * TILE * 3 + tid * 3;
            nx0 = __ldcs(nxp + 0); nx1 = __ldcs(nxp + 1); nx2 = __ldcs(nxp + 2);
            CP_WAIT(1);          // current tile's group complete
        } else {
            CP_WAIT(0);
        }
        __syncthreads();         // all threads' cp.async data visible

        const float* w = reinterpret_cast<const float*>(s_w[buf]);
        const float* h = reinterpret_cast<const float*>(s_h[buf]);

        float y0 = xr0, y1 = xr1, y2 = xr2;

        #pragma unroll
        for (int s = 0; s < 5; ++s) {
            const float w0 = w[tid * 15 + s * 3 + 0] * CW;
            const float w1 = w[tid * 15 + s * 3 + 1] * CW;
            const float w2 = w[tid * 15 + s * 3 + 2] * CW;
            const float h0 = h[tid * 15 + s * 3 + 0] * CH;
            const float h1 = h[tid * 15 + s * 3 + 1] * CH;
            const float h2 = h[tid * 15 + s * 3 + 2] * CH;

            const float z10 = y0 + h0;
            const float z11 = y1 + h1;
            const float z12 = y2 + h2;
            const float f10 = SIG * (z11 - z10);
            const float f11 = z10 * (RHO - z12) - z11;
            const float f12 = z10 * z11 - BET * z12;
            const float z20 = y0 + A56 * f10 + B56 * w0 + h0;
            const float z21 = y1 + A56 * f11 + B56 * w1 + h1;
            const float z22 = y2 + A56 * f12 + B56 * w2 + h2;
            const float f20 = SIG * (z21 - z20);
            const float f21 = z20 * (RHO - z22) - z21;
            const float f22 = z20 * z21 - BET * z22;
            y0 = y0 + DT * (0.4f * f10 + 0.6f * f20) + w0;
            y1 = y1 + DT * (0.4f * f11 + 0.6f * f21) + w1;
            y2 = y2 + DT * (0.4f * f12 + 0.6f * f22) + w2;
        }

        // direct streaming store (stride-3 scalar; warp covers contiguous
        // 384B so sectors are fully written -> no write-allocate reads;
        // R11 verified L2 merges partial sector writes at zero cost)
        float* op = g_out + (long long)tile * TILE * 3 + tid * 3;
        __stcs(op + 0, y0);
        __stcs(op + 1, y1);
        __stcs(op + 2, y2);

        // separates this tile's smem reads from the next prefetch that
        // overwrites this buffer.
        __syncthreads();

        xr0 = nx0; xr1 = nx1; xr2 = nx2;
        buf ^= 1;
    }
}

extern "C" void kernel_launch(void* const* d_in, const int* in_sizes, int n_in,
                              void* d_out, int out_size) {
    const float* x  = (const float*)d_in[0];
    const float* dW = (const float*)d_in[1];
    const float* dH = (const float*)d_in[2];
    float* out = (float*)d_out;

    const int n = in_sizes[0] / 3;        // 4194304, multiple of TILE
    const int n_tiles = n / TILE;         // 32768
    int grid = GRID;                      // exact 32 tiles/CTA, single wave
    if (grid > n_tiles) grid = n_tiles;
    lorenz_shark_kernel<<<grid, BLOCK>>>(x, dW, dH, out, n_tiles);
}